// round 1
// baseline (speedup 1.0000x reference)
#include <cuda_runtime.h>
#include <cstdint>

// Problem constants
#define T_STEPS 512
#define BATCH   64
#define INDIM   1024
#define HID     1024
#define G4      4096   // 4*HID

// Scan kernel config
#define NBLK     128
#define SCAN_THR 256
#define KC       64
#define WS_STR   34    // padded row stride for w smem [kk][col]

// xg GEMM config
#define XG_BM  128
#define XG_BN  64
#define XG_KC  32
#define XG_THR 512

// ---------------------------------------------------------------------------
// Global scratch (static __device__ arrays: allocation-free per harness rules)
// ---------------------------------------------------------------------------
__device__ float g_xg[(size_t)T_STEPS * BATCH * G4];  // 512 MB, [t][b][j'] (permuted cols)
__device__ float g_h[2][HID * BATCH];                 // double-buffered h, transposed [hj][b]
__device__ unsigned int g_count;
__device__ unsigned int g_sense;

// ---------------------------------------------------------------------------
// Packed f32x2 helpers (FFMA2 path — 2x fp32 MAC throughput vs scalar FFMA)
// ---------------------------------------------------------------------------
__device__ __forceinline__ unsigned long long pack2(float lo, float hi) {
    unsigned long long r;
    asm("mov.b64 %0, {%1, %2};" : "=l"(r) : "f"(lo), "f"(hi));
    return r;
}
__device__ __forceinline__ void fma2(unsigned long long& d,
                                     unsigned long long a,
                                     unsigned long long b) {
    asm("fma.rn.f32x2 %0, %1, %2, %0;" : "+l"(d) : "l"(a), "l"(b));
}
__device__ __forceinline__ float2 unpack2(unsigned long long v) {
    float2 r;
    asm("mov.b64 {%0, %1}, %2;" : "=f"(r.x), "=f"(r.y) : "l"(v));
    return r;
}

__device__ __forceinline__ float sigf(float x) {
    return __fdividef(1.0f, 1.0f + __expf(-x));
}
__device__ __forceinline__ float tanh_fast(float x) {
    // tanh(x) = 2*sigmoid(2x) - 1 ; ~1e-6 rel err (safer than tanh.approx)
    return __fdividef(2.0f, 1.0f + __expf(-2.0f * x)) - 1.0f;
}

// ---------------------------------------------------------------------------
// Reset: zero h buffers + barrier state (runs before every scan)
// ---------------------------------------------------------------------------
__global__ void reset_kernel() {
    int tid = blockIdx.x * blockDim.x + threadIdx.x;
    int nthr = gridDim.x * blockDim.x;
    float* hb = &g_h[0][0];
    for (int i = tid; i < 2 * HID * BATCH; i += nthr) hb[i] = 0.0f;
    if (tid == 0) { g_count = 0u; g_sense = 0u; }
}

// ---------------------------------------------------------------------------
// xg GEMM: g_xg[m][j'] = dot(x[m,:], W_ih[orig(j'),:]) + b_ih[orig] + b_hh[orig]
//   m = t*64+b (M=32768), j' = 4*hj + gate (permuted), K = 1024.
//   Tile 128x64, 512 threads, micro 4x4, row-paired FFMA2.
// ---------------------------------------------------------------------------
__global__ __launch_bounds__(XG_THR) void xg_gemm(
    const float* __restrict__ x,
    const float* __restrict__ Wih,
    const float* __restrict__ bih,
    const float* __restrict__ bhh)
{
    __shared__ float As[XG_KC][XG_BM + 4];  // [kk][m]
    __shared__ float Ws[XG_KC][XG_BN + 4];  // [kk][n']

    const int tid = threadIdx.x;
    const int tx  = tid & 15;   // col group: cols tx*4 .. tx*4+3
    const int ty  = tid >> 4;   // 0..31 row group: rows ty*4 .. ty*4+3
    const int n0  = blockIdx.x * XG_BN;
    const int m0  = blockIdx.y * XG_BM;

    // global-load assignments
    const int a_row  = tid >> 2;         // 0..127
    const int a_koff = (tid & 3) * 8;    // 0,8,16,24
    const int w_rowl = tid >> 3;         // 0..63
    const int w_koff = (tid & 7) * 4;    // 0..28

    const int np   = n0 + w_rowl;
    const int jo_w = (np & 3) * HID + (np >> 2);   // permuted -> original W_ih row
    const float* wrow = Wih + (size_t)jo_w * INDIM;
    const float* arow = x   + (size_t)(m0 + a_row) * INDIM;

    unsigned long long acc[2][4];
#pragma unroll
    for (int i = 0; i < 2; i++)
#pragma unroll
        for (int j = 0; j < 4; j++) acc[i][j] = 0ull;

    for (int kb = 0; kb < INDIM; kb += XG_KC) {
        __syncthreads();
        {   // stage A (transpose into [kk][m])
            float4 v0 = *reinterpret_cast<const float4*>(arow + kb + a_koff);
            float4 v1 = *reinterpret_cast<const float4*>(arow + kb + a_koff + 4);
            As[a_koff + 0][a_row] = v0.x;  As[a_koff + 1][a_row] = v0.y;
            As[a_koff + 2][a_row] = v0.z;  As[a_koff + 3][a_row] = v0.w;
            As[a_koff + 4][a_row] = v1.x;  As[a_koff + 5][a_row] = v1.y;
            As[a_koff + 6][a_row] = v1.z;  As[a_koff + 7][a_row] = v1.w;
        }
        {   // stage W (transpose into [kk][n'])
            float4 v = *reinterpret_cast<const float4*>(wrow + kb + w_koff);
            Ws[w_koff + 0][w_rowl] = v.x;  Ws[w_koff + 1][w_rowl] = v.y;
            Ws[w_koff + 2][w_rowl] = v.z;  Ws[w_koff + 3][w_rowl] = v.w;
        }
        __syncthreads();

#pragma unroll 8
        for (int kk = 0; kk < XG_KC; kk++) {
            ulonglong2 hp = *reinterpret_cast<const ulonglong2*>(&As[kk][ty * 4]);
            float4 wv = *reinterpret_cast<const float4*>(&Ws[kk][tx * 4]);
            unsigned long long w0 = pack2(wv.x, wv.x);
            unsigned long long w1 = pack2(wv.y, wv.y);
            unsigned long long w2 = pack2(wv.z, wv.z);
            unsigned long long w3 = pack2(wv.w, wv.w);
            fma2(acc[0][0], hp.x, w0);  fma2(acc[1][0], hp.y, w0);
            fma2(acc[0][1], hp.x, w1);  fma2(acc[1][1], hp.y, w1);
            fma2(acc[0][2], hp.x, w2);  fma2(acc[1][2], hp.y, w2);
            fma2(acc[0][3], hp.x, w3);  fma2(acc[1][3], hp.y, w3);
        }
    }

    // epilogue: + bias, store (coalesced float4)
    float bias[4];
#pragma unroll
    for (int cc = 0; cc < 4; cc++) {
        int np2 = n0 + tx * 4 + cc;
        int jo  = (np2 & 3) * HID + (np2 >> 2);
        bias[cc] = bih[jo] + bhh[jo];
    }
#pragma unroll
    for (int pr = 0; pr < 2; pr++) {
        float2 u0 = unpack2(acc[pr][0]);
        float2 u1 = unpack2(acc[pr][1]);
        float2 u2 = unpack2(acc[pr][2]);
        float2 u3 = unpack2(acc[pr][3]);
        int rowA = m0 + ty * 4 + pr * 2;
        float4 oa = make_float4(u0.x + bias[0], u1.x + bias[1], u2.x + bias[2], u3.x + bias[3]);
        float4 ob = make_float4(u0.y + bias[0], u1.y + bias[1], u2.y + bias[2], u3.y + bias[3]);
        *reinterpret_cast<float4*>(&g_xg[(size_t)rowA * G4 + n0 + tx * 4])       = oa;
        *reinterpret_cast<float4*>(&g_xg[(size_t)(rowA + 1) * G4 + n0 + tx * 4]) = ob;
    }
}

// ---------------------------------------------------------------------------
// Grid-wide barrier (sense-reversing; all NBLK blocks co-resident)
// ---------------------------------------------------------------------------
__device__ __forceinline__ void grid_bar(unsigned int target) {
    __syncthreads();
    if (threadIdx.x == 0) {
        __threadfence();
        unsigned int a = atomicAdd(&g_count, 1u);
        if (a == NBLK - 1) {
            atomicExch(&g_count, 0u);
            __threadfence();
            atomicExch(&g_sense, target);
        } else {
            volatile unsigned int* s = &g_sense;
            while (*s < target) { __nanosleep(32); }
            __threadfence();
        }
    }
    __syncthreads();
}

// ---------------------------------------------------------------------------
// Persistent LSTM scan.
//   Block jt owns permuted cols j' in [jt*32, jt*32+32) == hj in [jt*8, jt*8+8),
//   all 4 gates interleaved -> c stays in registers, h via double-buffered global.
//   gates[b][j'] = xg[t][b][j'] + sum_k h[k][b] * W_hh[orig(j')][k]
// ---------------------------------------------------------------------------
__global__ __launch_bounds__(SCAN_THR) void lstm_scan(
    const float* __restrict__ Whh,
    float* __restrict__ out)
{
    __shared__ float hs[KC * BATCH];   // [kk][b], stride 64
    __shared__ float ws[KC * WS_STR];  // [kk][col], stride 34 (8B-aligned rows)

    const int tid = threadIdx.x;
    const int tx  = tid & 15;     // col pair: cols 2tx, 2tx+1
    const int ty  = tid >> 4;     // row group: rows ty*4 .. ty*4+3
    const int jt  = blockIdx.x;
    const int j0  = jt * 32;
    const int b0  = ty * 4;

    // W staging assignment
    const int w_col  = tid >> 3;         // 0..31
    const int w_koff = (tid & 7) * 8;    // 0..56
    const int jp = j0 + w_col;
    const int jo = (jp & 3) * HID + (jp >> 2);
    const float* wrow = Whh + (size_t)jo * HID;

    const int  hj  = jt * 8 + (tx >> 1);
    const bool upd = ((tx & 1) == 0);    // even lanes own (i,f) and do the state update

    float c[4] = {0.f, 0.f, 0.f, 0.f};
    const float* xgcol = g_xg + j0 + tx * 2;

    for (int t = 0; t < T_STEPS; t++) {
        const int cur = t & 1, nxt = cur ^ 1;
        unsigned long long a00 = 0ull, a01 = 0ull, a10 = 0ull, a11 = 0ull;
        const float* hsrc = g_h[cur];

        for (int kb = 0; kb < HID; kb += KC) {
            __syncthreads();
            {   // stage h chunk: straight copy of KC*64 contiguous floats (L2-coherent)
                const float4* hg = reinterpret_cast<const float4*>(hsrc + kb * BATCH);
                float4* hd = reinterpret_cast<float4*>(hs);
#pragma unroll
                for (int u = 0; u < 4; u++)
                    hd[tid + 256 * u] = __ldcg(hg + tid + 256 * u);
            }
            {   // stage W chunk (transpose into [kk][col])
                float4 v0 = *reinterpret_cast<const float4*>(wrow + kb + w_koff);
                float4 v1 = *reinterpret_cast<const float4*>(wrow + kb + w_koff + 4);
                ws[(w_koff + 0) * WS_STR + w_col] = v0.x;
                ws[(w_koff + 1) * WS_STR + w_col] = v0.y;
                ws[(w_koff + 2) * WS_STR + w_col] = v0.z;
                ws[(w_koff + 3) * WS_STR + w_col] = v0.w;
                ws[(w_koff + 4) * WS_STR + w_col] = v1.x;
                ws[(w_koff + 5) * WS_STR + w_col] = v1.y;
                ws[(w_koff + 6) * WS_STR + w_col] = v1.z;
                ws[(w_koff + 7) * WS_STR + w_col] = v1.w;
            }
            __syncthreads();

#pragma unroll 16
            for (int kk = 0; kk < KC; kk++) {
                ulonglong2 hp = *reinterpret_cast<const ulonglong2*>(&hs[kk * BATCH + b0]);
                float2 wv = *reinterpret_cast<const float2*>(&ws[kk * WS_STR + tx * 2]);
                unsigned long long w0 = pack2(wv.x, wv.x);
                unsigned long long w1 = pack2(wv.y, wv.y);
                fma2(a00, hp.x, w0);
                fma2(a10, hp.y, w0);
                fma2(a01, hp.x, w1);
                fma2(a11, hp.y, w1);
            }
        }

        // ---- epilogue: add xg, swap gate halves between lane pairs, update c/h ----
        float2 p0 = unpack2(a00), p1 = unpack2(a10);   // col 2tx,   rows b0..b0+3
        float2 q0 = unpack2(a01), q1 = unpack2(a11);   // col 2tx+1, rows b0..b0+3
        float ga[4] = { p0.x, p0.y, p1.x, p1.y };
        float gb[4] = { q0.x, q0.y, q1.x, q1.y };

        const float* xgp = xgcol + (size_t)t * (BATCH * G4);
#pragma unroll
        for (int rr = 0; rr < 4; rr++) {
            float2 xv = *reinterpret_cast<const float2*>(xgp + (size_t)(b0 + rr) * G4);
            ga[rr] += xv.x;
            gb[rr] += xv.y;
        }

        float hn[4];
#pragma unroll
        for (int rr = 0; rr < 4; rr++) {
            // even lane: own cols = (i, f); partner (odd lane) holds (g, o)
            float pg = __shfl_xor_sync(0xffffffffu, ga[rr], 1);
            float po = __shfl_xor_sync(0xffffffffu, gb[rr], 1);
            float ig = sigf(ga[rr]);
            float fg = sigf(gb[rr]);
            float gg = tanh_fast(pg);
            float og = sigf(po);
            c[rr]  = fg * c[rr] + ig * gg;
            hn[rr] = og * tanh_fast(c[rr]);
        }

        if (upd) {
            *reinterpret_cast<float4*>(&g_h[nxt][hj * BATCH + b0]) =
                make_float4(hn[0], hn[1], hn[2], hn[3]);
            if (t == T_STEPS - 1) {
#pragma unroll
                for (int rr = 0; rr < 4; rr++)
                    out[(b0 + rr) * HID + hj] = hn[rr];
            }
        }

        if (t != T_STEPS - 1) grid_bar((unsigned int)(t + 1));
    }
}

// ---------------------------------------------------------------------------
// Launch
// ---------------------------------------------------------------------------
extern "C" void kernel_launch(void* const* d_in, const int* in_sizes, int n_in,
                              void* d_out, int out_size) {
    const float* x   = (const float*)d_in[0];
    const float* Wih = (const float*)d_in[1];
    const float* Whh = (const float*)d_in[2];
    const float* bih = (const float*)d_in[3];
    const float* bhh = (const float*)d_in[4];
    float* out = (float*)d_out;

    reset_kernel<<<64, 256>>>();
    xg_gemm<<<dim3(G4 / XG_BN, (T_STEPS * BATCH) / XG_BM), XG_THR>>>(x, Wih, bih, bhh);
    lstm_scan<<<NBLK, SCAN_THR>>>(Whh, out);
}

// round 2
// speedup vs baseline: 1.2562x; 1.2562x over previous
#include <cuda_runtime.h>
#include <cstdint>

#define T_STEPS 512
#define BATCH   64
#define INDIM   1024
#define HID     1024
#define G4      4096

// scan config
#define NBLK     128
#define SCAN_THR 256
#define KC       64
// xg config
#define XG_BM  128
#define XG_BN  64
#define XG_KC  32
#define XG_THR 512

// ---------------------------------------------------------------------------
__device__ float g_xg[(size_t)T_STEPS * BATCH * G4];  // [t][b][j'] permuted
__device__ float g_h[2][HID * BATCH];                 // [hj][b], double buffered
__device__ unsigned int g_count;
__device__ unsigned int g_sense;

// packed f32x2 helpers
__device__ __forceinline__ unsigned long long pack2(float lo, float hi) {
    unsigned long long r;
    asm("mov.b64 %0, {%1, %2};" : "=l"(r) : "f"(lo), "f"(hi));
    return r;
}
__device__ __forceinline__ void fma2(unsigned long long& d,
                                     unsigned long long a,
                                     unsigned long long b) {
    asm("fma.rn.f32x2 %0, %1, %2, %0;" : "+l"(d) : "l"(a), "l"(b));
}
__device__ __forceinline__ void add2(unsigned long long& d, unsigned long long a) {
    asm("add.rn.f32x2 %0, %0, %1;" : "+l"(d) : "l"(a));
}
__device__ __forceinline__ float2 unpack2(unsigned long long v) {
    float2 r;
    asm("mov.b64 {%0, %1}, %2;" : "=f"(r.x), "=f"(r.y) : "l"(v));
    return r;
}
__device__ __forceinline__ float sigf(float x) {
    return __fdividef(1.0f, 1.0f + __expf(-x));
}
__device__ __forceinline__ float tanh_fast(float x) {
    return __fdividef(2.0f, 1.0f + __expf(-2.0f * x)) - 1.0f;
}

// ---------------------------------------------------------------------------
// xg GEMM (+ fused reset of h / barrier state).
//   g_xg[m][j'] = x[m,:] . W_ih[orig(j'),:] + b_ih + b_hh,  j' = 4*hj + gate.
//   Tile 128x64, 512 thr, micro 4x4 row-paired FFMA2, reg double-buffering.
// ---------------------------------------------------------------------------
__global__ __launch_bounds__(XG_THR, 2) void xg_gemm(
    const float* __restrict__ x,
    const float* __restrict__ Wih,
    const float* __restrict__ bih,
    const float* __restrict__ bhh)
{
    __shared__ float As[2][XG_KC][XG_BM];  // [buf][kk][m], stride 128
    __shared__ float Ws[2][XG_KC][XG_BN];  // [buf][kk][n'], stride 64

    const int tid = threadIdx.x;
    const int tx  = tid & 15;    // cols tx*4..+3
    const int ty  = tid >> 4;    // rows ty*4..+3
    const int n0  = blockIdx.x * XG_BN;
    const int m0  = blockIdx.y * XG_BM;

    // fused reset (block 0 only; scan launches after this kernel completes)
    if (blockIdx.x == 0 && blockIdx.y == 0) {
        float4* hz = reinterpret_cast<float4*>(&g_h[0][0]);
#pragma unroll
        for (int u = 0; u < 32; u++) hz[tid + XG_THR * u] = make_float4(0.f, 0.f, 0.f, 0.f);
        if (tid == 0) { g_count = 0u; g_sense = 0u; }
    }

    // staging mappings: lanes consecutive in row -> conflict-free STS,
    // 32B/lane (A) contiguous loads -> full-sector LDG.
    const int a_row = tid & 127;
    const int a_k8  = (tid >> 7) * 8;     // 0,8,16,24
    const int w_row = tid & 63;
    const int w_k4  = (tid >> 6) * 4;     // 0,4,...,28

    const int np   = n0 + w_row;
    const int jo_w = (np & 3) * HID + (np >> 2);
    const float* wrow = Wih + (size_t)jo_w * INDIM;
    const float* arow = x   + (size_t)(m0 + a_row) * INDIM;

    unsigned long long acc[2][4];
#pragma unroll
    for (int i = 0; i < 2; i++)
#pragma unroll
        for (int j = 0; j < 4; j++) acc[i][j] = 0ull;

    // prefetch tile 0
    float4 pa0 = *reinterpret_cast<const float4*>(arow + a_k8);
    float4 pa1 = *reinterpret_cast<const float4*>(arow + a_k8 + 4);
    float4 pw  = *reinterpret_cast<const float4*>(wrow + w_k4);

    int buf = 0;
#pragma unroll 1
    for (int kb = 0; kb < INDIM; kb += XG_KC) {
        // stage current tile
        As[buf][a_k8 + 0][a_row] = pa0.x;  As[buf][a_k8 + 1][a_row] = pa0.y;
        As[buf][a_k8 + 2][a_row] = pa0.z;  As[buf][a_k8 + 3][a_row] = pa0.w;
        As[buf][a_k8 + 4][a_row] = pa1.x;  As[buf][a_k8 + 5][a_row] = pa1.y;
        As[buf][a_k8 + 6][a_row] = pa1.z;  As[buf][a_k8 + 7][a_row] = pa1.w;
        Ws[buf][w_k4 + 0][w_row] = pw.x;   Ws[buf][w_k4 + 1][w_row] = pw.y;
        Ws[buf][w_k4 + 2][w_row] = pw.z;   Ws[buf][w_k4 + 3][w_row] = pw.w;
        __syncthreads();

        if (kb + XG_KC < INDIM) {  // prefetch next tile (latency hidden by compute)
            pa0 = *reinterpret_cast<const float4*>(arow + kb + XG_KC + a_k8);
            pa1 = *reinterpret_cast<const float4*>(arow + kb + XG_KC + a_k8 + 4);
            pw  = *reinterpret_cast<const float4*>(wrow + kb + XG_KC + w_k4);
        }

#pragma unroll 8
        for (int kk = 0; kk < XG_KC; kk++) {
            ulonglong2 hp = *reinterpret_cast<const ulonglong2*>(&As[buf][kk][ty * 4]);
            float4 wv = *reinterpret_cast<const float4*>(&Ws[buf][kk][tx * 4]);
            unsigned long long w0 = pack2(wv.x, wv.x);
            unsigned long long w1 = pack2(wv.y, wv.y);
            unsigned long long w2 = pack2(wv.z, wv.z);
            unsigned long long w3 = pack2(wv.w, wv.w);
            fma2(acc[0][0], hp.x, w0);  fma2(acc[1][0], hp.y, w0);
            fma2(acc[0][1], hp.x, w1);  fma2(acc[1][1], hp.y, w1);
            fma2(acc[0][2], hp.x, w2);  fma2(acc[1][2], hp.y, w2);
            fma2(acc[0][3], hp.x, w3);  fma2(acc[1][3], hp.y, w3);
        }
        buf ^= 1;
    }

    float bias[4];
#pragma unroll
    for (int cc = 0; cc < 4; cc++) {
        int np2 = n0 + tx * 4 + cc;
        int jo  = (np2 & 3) * HID + (np2 >> 2);
        bias[cc] = bih[jo] + bhh[jo];
    }
#pragma unroll
    for (int pr = 0; pr < 2; pr++) {
        float2 u0 = unpack2(acc[pr][0]);
        float2 u1 = unpack2(acc[pr][1]);
        float2 u2 = unpack2(acc[pr][2]);
        float2 u3 = unpack2(acc[pr][3]);
        int rowA = m0 + ty * 4 + pr * 2;
        float4 oa = make_float4(u0.x + bias[0], u1.x + bias[1], u2.x + bias[2], u3.x + bias[3]);
        float4 ob = make_float4(u0.y + bias[0], u1.y + bias[1], u2.y + bias[2], u3.y + bias[3]);
        *reinterpret_cast<float4*>(&g_xg[(size_t)rowA * G4 + n0 + tx * 4])       = oa;
        *reinterpret_cast<float4*>(&g_xg[(size_t)(rowA + 1) * G4 + n0 + tx * 4]) = ob;
    }
}

// ---------------------------------------------------------------------------
// grid barrier (sense-reversing, all NBLK co-resident)
// ---------------------------------------------------------------------------
__device__ __forceinline__ void grid_bar(unsigned int target) {
    __syncthreads();
    if (threadIdx.x == 0) {
        __threadfence();
        unsigned int a = atomicAdd(&g_count, 1u);
        if (a == NBLK - 1) {
            atomicExch(&g_count, 0u);
            __threadfence();
            atomicExch(&g_sense, target);
        } else {
            volatile unsigned int* s = &g_sense;
            while (*s < target) { __nanosleep(16); }
            __threadfence();
        }
    }
    __syncthreads();
}

// ---------------------------------------------------------------------------
// Persistent LSTM scan.
//   Block jt owns 32 permuted cols = 8 hj (4 gates each, gate-aligned per thread
//   -> no shfl). W_hh slice (128 KB) persistent in smem. K split across two
//   128-thread halves; h chunks double-buffered; xg prefetched per step.
// ---------------------------------------------------------------------------
#define SCAN_SMEM_FLOATS (32768 + 16384 + 2048)   // ws + hs[2][2] + red = 200 KB

__global__ __launch_bounds__(SCAN_THR) void lstm_scan(
    const float* __restrict__ Whh,
    float* __restrict__ out)
{
    extern __shared__ float sm[];
    float* ws  = sm;                    // [1024][32]
    float* hsA = sm + 32768;            // [half][buf][64*64] -> 4 x 4096 floats
    float* red = sm + 32768 + 16384;    // [128][16]

    const int tid = threadIdx.x;
    const int ks  = tid >> 7;           // K-half: 0 or 1
    const int txy = tid & 127;
    const int tx  = txy & 7;            // hj-local (4 gate cols)
    const int ty  = txy >> 3;           // rows ty*4..+3
    const int b0  = ty * 4;
    const int c0  = tx * 4;
    const int jt  = blockIdx.x;
    const int j0  = jt * 32;
    const int hj  = jt * 8 + tx;

    // --- persistent W_hh preload: ws[k][col], col = permuted local column ---
    {
        const int wcol  = tid & 31;
        const int kpart = tid >> 5;       // 8 parts x 128 k
        const int jp = j0 + wcol;
        const int jo = (jp & 3) * HID + (jp >> 2);
        const float* wr = Whh + (size_t)jo * HID + kpart * 128;
#pragma unroll 8
        for (int i = 0; i < 128; i += 4) {
            float4 v = *reinterpret_cast<const float4*>(wr + i);
            int k = kpart * 128 + i;
            ws[(k + 0) * 32 + wcol] = v.x;
            ws[(k + 1) * 32 + wcol] = v.y;
            ws[(k + 2) * 32 + wcol] = v.z;
            ws[(k + 3) * 32 + wcol] = v.w;
        }
    }
    __syncthreads();

    const float* wsme = ws + (ks * 512) * 32;  // this half's K range

    float c_[4] = {0.f, 0.f, 0.f, 0.f};
    int buf = 0;

#pragma unroll 1
    for (int t = 0; t < T_STEPS; t++) {
        const int cur = t & 1, nxt = cur ^ 1;
        const float* hsrc = g_h[cur];

        // prefetch xg epilogue values early (DRAM latency hidden by k-loop)
        float4 xr[4];
        if (ks == 0) {
            const float* xgp = g_xg + (size_t)t * (BATCH * G4) + j0 + c0;
#pragma unroll
            for (int r = 0; r < 4; r++)
                xr[r] = *reinterpret_cast<const float4*>(xgp + (size_t)(b0 + r) * G4);
        }

        unsigned long long acc[2][4];
#pragma unroll
        for (int p = 0; p < 2; p++)
#pragma unroll
            for (int cc = 0; cc < 4; cc++) acc[p][cc] = 0ull;

        // prefetch h chunk 0 of this half
        float4 hr[8];
        {
            const float4* hg = reinterpret_cast<const float4*>(hsrc + (ks * 512) * BATCH);
#pragma unroll
            for (int u = 0; u < 8; u++) hr[u] = __ldcg(hg + txy + 128 * u);
        }

#pragma unroll 1
        for (int cidx = 0; cidx < 8; cidx++) {
            float* hb = hsA + (ks * 2 + buf) * 4096;
            {
                float4* hd = reinterpret_cast<float4*>(hb);
#pragma unroll
                for (int u = 0; u < 8; u++) hd[txy + 128 * u] = hr[u];
            }
            __syncthreads();

            if (cidx < 7) {  // prefetch next chunk
                const float4* hg = reinterpret_cast<const float4*>(
                    hsrc + (ks * 512 + (cidx + 1) * KC) * BATCH);
#pragma unroll
                for (int u = 0; u < 8; u++) hr[u] = __ldcg(hg + txy + 128 * u);
            }

            const float* wsc = wsme + (cidx * KC) * 32;
#pragma unroll 16
            for (int kk = 0; kk < KC; kk++) {
                ulonglong2 hp = *reinterpret_cast<const ulonglong2*>(hb + kk * BATCH + b0);
                float4 wv = *reinterpret_cast<const float4*>(wsc + kk * 32 + c0);
                unsigned long long w0 = pack2(wv.x, wv.x);
                unsigned long long w1 = pack2(wv.y, wv.y);
                unsigned long long w2 = pack2(wv.z, wv.z);
                unsigned long long w3 = pack2(wv.w, wv.w);
                fma2(acc[0][0], hp.x, w0);  fma2(acc[1][0], hp.y, w0);
                fma2(acc[0][1], hp.x, w1);  fma2(acc[1][1], hp.y, w1);
                fma2(acc[0][2], hp.x, w2);  fma2(acc[1][2], hp.y, w2);
                fma2(acc[0][3], hp.x, w3);  fma2(acc[1][3], hp.y, w3);
            }
            buf ^= 1;
        }

        // K-split reduction: half1 -> smem, half0 adds
        if (ks == 1) {
            ulonglong2* rp = reinterpret_cast<ulonglong2*>(red + txy * 16);
            rp[0] = make_ulonglong2(acc[0][0], acc[0][1]);
            rp[1] = make_ulonglong2(acc[0][2], acc[0][3]);
            rp[2] = make_ulonglong2(acc[1][0], acc[1][1]);
            rp[3] = make_ulonglong2(acc[1][2], acc[1][3]);
        }
        __syncthreads();

        if (ks == 0) {
            const ulonglong2* rp = reinterpret_cast<const ulonglong2*>(red + txy * 16);
            ulonglong2 r0 = rp[0], r1 = rp[1], r2 = rp[2], r3 = rp[3];
            add2(acc[0][0], r0.x);  add2(acc[0][1], r0.y);
            add2(acc[0][2], r1.x);  add2(acc[0][3], r1.y);
            add2(acc[1][0], r2.x);  add2(acc[1][1], r2.y);
            add2(acc[1][2], r3.x);  add2(acc[1][3], r3.y);

            // gates: cc = 0:i 1:f 2:g 3:o (permuted layout j' = 4*hj + gate)
            float gt[4][4];
#pragma unroll
            for (int cc = 0; cc < 4; cc++) {
                float2 lo = unpack2(acc[0][cc]);
                float2 hi = unpack2(acc[1][cc]);
                gt[0][cc] = lo.x;  gt[1][cc] = lo.y;
                gt[2][cc] = hi.x;  gt[3][cc] = hi.y;
            }
            float hn[4];
#pragma unroll
            for (int r = 0; r < 4; r++) {
                float gi = sigf(gt[r][0] + xr[r].x);
                float gf = sigf(gt[r][1] + xr[r].y);
                float gg = tanh_fast(gt[r][2] + xr[r].z);
                float go = sigf(gt[r][3] + xr[r].w);
                c_[r]  = gf * c_[r] + gi * gg;
                hn[r]  = go * tanh_fast(c_[r]);
            }
            *reinterpret_cast<float4*>(&g_h[nxt][hj * BATCH + b0]) =
                make_float4(hn[0], hn[1], hn[2], hn[3]);
            if (t == T_STEPS - 1) {
#pragma unroll
                for (int r = 0; r < 4; r++)
                    out[(b0 + r) * HID + hj] = hn[r];
            }
        }

        if (t != T_STEPS - 1) grid_bar((unsigned int)(t + 1));
    }
}

// ---------------------------------------------------------------------------
extern "C" void kernel_launch(void* const* d_in, const int* in_sizes, int n_in,
                              void* d_out, int out_size) {
    const float* x   = (const float*)d_in[0];
    const float* Wih = (const float*)d_in[1];
    const float* Whh = (const float*)d_in[2];
    const float* bih = (const float*)d_in[3];
    const float* bhh = (const float*)d_in[4];
    float* out = (float*)d_out;

    static_assert(SCAN_SMEM_FLOATS * 4 == 204800, "smem layout");
    cudaFuncSetAttribute(lstm_scan, cudaFuncAttributeMaxDynamicSharedMemorySize,
                         SCAN_SMEM_FLOATS * 4);

    xg_gemm<<<dim3(G4 / XG_BN, (T_STEPS * BATCH) / XG_BM), XG_THR>>>(x, Wih, bih, bhh);
    lstm_scan<<<NBLK, SCAN_THR, SCAN_SMEM_FLOATS * 4>>>(Whh, out);
}